// round 15
// baseline (speedup 1.0000x reference)
#include <cuda_runtime.h>
#include <cuda_bf16.h>
#include <cstdint>

#define N_ROWS 16384
#define N_CODES 4096
#define DIM 1024

#define CAP 512                 // candidate list capacity per row
#define MARGIN 14.0f            // >= 2E = 12.6 (worst-case bf16 pair error) + slop
#define TIGHT  12.8f            // >= 2E; singleton within TIGHT -> provably argmin

#define KC 64                   // dims per chunk (64 bf16 = 128B rows, SW128)
#define N_DC (DIM / KC)         // 16 chunks
#define STAGES 3

// ---------------- device scratch (static; no allocation allowed) ----------------
__device__ __nv_bfloat16 g_Xb[N_ROWS * DIM];    // 32 MB
__device__ __nv_bfloat16 g_Eb[N_CODES * DIM];   // 8 MB
__device__ float g_enorm2[N_CODES];
__device__ unsigned int g_rowmin_key[N_ROWS];
__device__ unsigned int g_cand_cnt[N_ROWS];
__device__ unsigned long long g_cand[(size_t)N_ROWS * CAP];  // 64 MB

// ---------------- helpers ----------------
__device__ __forceinline__ unsigned int fkey(float f) {
    unsigned int u = __float_as_uint(f);
    return (u & 0x80000000u) ? ~u : (u | 0x80000000u);
}
__device__ __forceinline__ float inv_fkey(unsigned int k) {
    unsigned int u = (k & 0x80000000u) ? (k ^ 0x80000000u) : ~k;
    return __uint_as_float(u);
}
__device__ __forceinline__ uint32_t smem_u32(const void* p) {
    uint32_t a;
    asm("{ .reg .u64 t; cvta.to.shared.u64 t, %1; cvt.u32.u64 %0, t; }" : "=r"(a) : "l"(p));
    return a;
}
#define SWZ(x) ((x) ^ (((x) >> 3) & 0x70))

__device__ __forceinline__ void cp_async16(uint32_t dst, const void* src) {
    asm volatile("cp.async.cg.shared.global [%0], [%1], 16;"
                 :: "r"(dst), "l"((unsigned long long)__cvta_generic_to_global(src)) : "memory");
}
#define CP_COMMIT()  asm volatile("cp.async.commit_group;" ::: "memory")
#define CP_WAIT(n)   asm volatile("cp.async.wait_group %0;" :: "n"(n) : "memory")

__device__ __forceinline__ void ldmatrix_x4(uint32_t& r0, uint32_t& r1, uint32_t& r2,
                                            uint32_t& r3, uint32_t addr) {
    asm volatile("ldmatrix.sync.aligned.m8n8.x4.shared.b16 {%0,%1,%2,%3}, [%4];"
                 : "=r"(r0), "=r"(r1), "=r"(r2), "=r"(r3) : "r"(addr));
}
__device__ __forceinline__ void mma_16816(float* c, const uint32_t* a, uint32_t b0, uint32_t b1) {
    asm volatile("mma.sync.aligned.m16n8k16.row.col.f32.bf16.bf16.f32 "
                 "{%0,%1,%2,%3}, {%4,%5,%6,%7}, {%8,%9}, {%0,%1,%2,%3};"
                 : "+f"(c[0]), "+f"(c[1]), "+f"(c[2]), "+f"(c[3])
                 : "r"(a[0]), "r"(a[1]), "r"(a[2]), "r"(a[3]), "r"(b0), "r"(b1));
}

// ---------------- phase 0: fused X-convert + state init + E-convert + norms ----
#define XCONV_BLOCKS 2048
__global__ __launch_bounds__(256) void conv_all(const float* __restrict__ X,
                                                const float* __restrict__ E,
                                                __nv_bfloat16* __restrict__ Xb,
                                                __nv_bfloat16* __restrict__ Eb) {
    if (blockIdx.x < XCONV_BLOCKS) {
        int i = blockIdx.x * 256 + threadIdx.x;
        if (i < N_ROWS) { g_rowmin_key[i] = 0xFFFFFFFFu; g_cand_cnt[i] = 0u; }
        const int n4 = N_ROWS * DIM / 4;
        for (; i < n4; i += XCONV_BLOCKS * 256) {
            float4 v = ((const float4*)X)[i];
            ((__nv_bfloat162*)Xb)[i * 2]     = __floats2bfloat162_rn(v.x, v.y);
            ((__nv_bfloat162*)Xb)[i * 2 + 1] = __floats2bfloat162_rn(v.z, v.w);
        }
    } else {
        const int k = (blockIdx.x - XCONV_BLOCKS) * 8 + (threadIdx.x >> 5);
        const int lane = threadIdx.x & 31;
        const float4* row = (const float4*)(E + (size_t)k * DIM);
        __nv_bfloat162* drow = (__nv_bfloat162*)(Eb + (size_t)k * DIM);
        float s = 0.f;
#pragma unroll
        for (int i = 0; i < 8; i++) {
            float4 v = row[lane + i * 32];
            s = fmaf(v.x, v.x, s); s = fmaf(v.y, v.y, s);
            s = fmaf(v.z, v.z, s); s = fmaf(v.w, v.w, s);
            drow[(lane + i * 32) * 2]     = __floats2bfloat162_rn(v.x, v.y);
            drow[(lane + i * 32) * 2 + 1] = __floats2bfloat162_rn(v.z, v.w);
        }
#pragma unroll
        for (int off = 16; off > 0; off >>= 1) s += __shfl_xor_sync(0xffffffffu, s, off);
        if (lane == 0) g_enorm2[k] = s;
    }
}

// ---------------- phase 1: HMMA bf16 GEMM + candidate epilogue ----------------
#define BUF_STRIDE 32768u
#define SMEM_NEED  98304

__device__ __forceinline__ void load_chunk_A(uint32_t base, int buf, int m0, int dc, int tid) {
    const uint32_t aB = base + buf * BUF_STRIDE;
    const __nv_bfloat16* Xsrc = g_Xb + (size_t)m0 * DIM + dc * KC;
#pragma unroll
    for (int p = 0; p < 4; p++) {
        int s = tid + p * 256;
        int r = s >> 3, c = s & 7;
        cp_async16(aB + SWZ((uint32_t)(r * 128 + c * 16)), Xsrc + (size_t)r * DIM + c * 8);
    }
}
__device__ __forceinline__ void load_chunk_B(uint32_t base, int buf, int k0, int dc, int tid) {
    const uint32_t bB = base + buf * BUF_STRIDE + 16384u;
    const __nv_bfloat16* Esrc = g_Eb + (size_t)k0 * DIM + dc * KC;
#pragma unroll
    for (int p = 0; p < 4; p++) {
        int s = tid + p * 256;
        int r = s >> 3, c = s & 7;
        cp_async16(bB + SWZ((uint32_t)(r * 128 + c * 16)), Esrc + (size_t)r * DIM + c * 8);
    }
}

__global__ __launch_bounds__(256, 2) void vq_hmma_kernel() {
    extern __shared__ char smraw[];
    const uint32_t base = smem_u32(smraw);

    const int tid = threadIdx.x;
    const int wid = tid >> 5;
    const int lane = tid & 31;
    const int wm = wid & 3;          // warp M index (4)
    const int wn = wid >> 2;         // warp N index (2)
    const int m0 = blockIdx.y * 128;
    const int k0 = blockIdx.x * 128;

    float c[2][8][4];
#pragma unroll
    for (int i = 0; i < 2; i++)
#pragma unroll
        for (int j = 0; j < 8; j++)
#pragma unroll
            for (int e = 0; e < 4; e++) c[i][j][e] = 0.f;

    const int a_row = wm * 32 + (lane & 15);
    const int a_colb = (lane >> 4) * 16;
    const int bg = lane >> 3;
    const int b_row_base = wn * 64 + ((bg >> 1) * 8) + (lane & 7);
    const int b_colb = (bg & 1) * 16;

    load_chunk_A(base, 0, m0, 0, tid);
    load_chunk_B(base, 0, k0, 0, tid);
    CP_COMMIT();
    load_chunk_A(base, 1, m0, 1, tid);
    load_chunk_B(base, 1, k0, 1, tid);
    CP_COMMIT();

    for (int dc = 0; dc < N_DC; dc++) {
        if (dc + 1 < N_DC) CP_WAIT(1); else CP_WAIT(0);
        __syncthreads();

        const uint32_t aB = base + (dc % STAGES) * BUF_STRIDE;
        const uint32_t bB = aB + 16384u;
        const bool pf = (dc + 2 < N_DC);
        const int pbuf = (dc + 2) % STAGES;

        // kk = 0: tensor pipe first
        {
            uint32_t a[2][4];
#pragma unroll
            for (int i = 0; i < 2; i++)
                ldmatrix_x4(a[i][0], a[i][1], a[i][2], a[i][3],
                            aB + SWZ((uint32_t)((a_row + i * 16) * 128 + a_colb)));
            uint32_t b[4][4];
#pragma unroll
            for (int j2 = 0; j2 < 4; j2++)
                ldmatrix_x4(b[j2][0], b[j2][1], b[j2][2], b[j2][3],
                            bB + SWZ((uint32_t)((b_row_base + j2 * 16) * 128 + b_colb)));
#pragma unroll
            for (int i = 0; i < 2; i++)
#pragma unroll
                for (int j2 = 0; j2 < 4; j2++) {
                    mma_16816(c[i][j2 * 2],     a[i], b[j2][0], b[j2][1]);
                    mma_16816(c[i][j2 * 2 + 1], a[i], b[j2][2], b[j2][3]);
                }
        }

        // first half of prefetch (A tile of chunk dc+2)
        if (pf) load_chunk_A(base, pbuf, m0, dc + 2, tid);

        // kk = 1
        {
            const int kk = 1;
            uint32_t a[2][4];
#pragma unroll
            for (int i = 0; i < 2; i++)
                ldmatrix_x4(a[i][0], a[i][1], a[i][2], a[i][3],
                            aB + SWZ((uint32_t)((a_row + i * 16) * 128 + kk * 32 + a_colb)));
            uint32_t b[4][4];
#pragma unroll
            for (int j2 = 0; j2 < 4; j2++)
                ldmatrix_x4(b[j2][0], b[j2][1], b[j2][2], b[j2][3],
                            bB + SWZ((uint32_t)((b_row_base + j2 * 16) * 128 + kk * 32 + b_colb)));
#pragma unroll
            for (int i = 0; i < 2; i++)
#pragma unroll
                for (int j2 = 0; j2 < 4; j2++) {
                    mma_16816(c[i][j2 * 2],     a[i], b[j2][0], b[j2][1]);
                    mma_16816(c[i][j2 * 2 + 1], a[i], b[j2][2], b[j2][3]);
                }
        }

        // second half of prefetch (B tile) + single commit for the whole chunk
        if (pf) {
            load_chunk_B(base, pbuf, k0, dc + 2, tid);
            CP_COMMIT();
        }

#pragma unroll
        for (int kk = 2; kk < 4; kk++) {
            uint32_t a[2][4];
#pragma unroll
            for (int i = 0; i < 2; i++)
                ldmatrix_x4(a[i][0], a[i][1], a[i][2], a[i][3],
                            aB + SWZ((uint32_t)((a_row + i * 16) * 128 + kk * 32 + a_colb)));
            uint32_t b[4][4];
#pragma unroll
            for (int j2 = 0; j2 < 4; j2++)
                ldmatrix_x4(b[j2][0], b[j2][1], b[j2][2], b[j2][3],
                            bB + SWZ((uint32_t)((b_row_base + j2 * 16) * 128 + kk * 32 + b_colb)));
#pragma unroll
            for (int i = 0; i < 2; i++)
#pragma unroll
                for (int j2 = 0; j2 < 4; j2++) {
                    mma_16816(c[i][j2 * 2],     a[i], b[j2][0], b[j2][1]);
                    mma_16816(c[i][j2 * 2 + 1], a[i], b[j2][2], b[j2][3]);
                }
        }
    }

    // ---- epilogue ----
    const int qrow = lane >> 2;
    const int qcol = (lane & 3) * 2;

    float rmin[4] = {__int_as_float(0x7f800000), __int_as_float(0x7f800000),
                     __int_as_float(0x7f800000), __int_as_float(0x7f800000)};
#pragma unroll
    for (int i = 0; i < 2; i++)
#pragma unroll
        for (int j = 0; j < 8; j++) {
            const int colb = k0 + wn * 64 + j * 8 + qcol;
            const float en0 = __ldg(&g_enorm2[colb]);
            const float en1 = __ldg(&g_enorm2[colb + 1]);
#pragma unroll
            for (int e = 0; e < 4; e++) {
                const float s = fmaf(-2.f, c[i][j][e], (e & 1) ? en1 : en0);
                c[i][j][e] = s;
                const int r = i * 2 + (e >> 1);
                rmin[r] = fminf(rmin[r], s);
            }
        }
#pragma unroll
    for (int r = 0; r < 4; r++) {
#pragma unroll
        for (int off = 1; off < 4; off <<= 1)
            rmin[r] = fminf(rmin[r], __shfl_xor_sync(0xffffffffu, rmin[r], off));
    }
    int rows[4];
#pragma unroll
    for (int r = 0; r < 4; r++)
        rows[r] = m0 + wm * 32 + (r >> 1) * 16 + qrow + (r & 1) * 8;

    if ((lane & 3) == 0) {
#pragma unroll
        for (int r = 0; r < 4; r++) {
            const unsigned key = fkey(rmin[r]);
            if (key < g_rowmin_key[rows[r]])          // cheap L2 read filters ~97% of atomics
                atomicMin(&g_rowmin_key[rows[r]], key);
        }
    }

    float thr[4];
#pragma unroll
    for (int r = 0; r < 4; r++) {
        const float g = inv_fkey(g_rowmin_key[rows[r]]);
        thr[r] = fminf(rmin[r], g) + MARGIN;
    }
#pragma unroll
    for (int i = 0; i < 2; i++)
#pragma unroll
        for (int j = 0; j < 8; j++)
#pragma unroll
            for (int e = 0; e < 4; e++) {
                const int r = i * 2 + (e >> 1);
                const float s = c[i][j][e];
                if (s <= thr[r]) {
                    const int row = rows[r];
                    const int col = k0 + wn * 64 + j * 8 + qcol + (e & 1);
                    unsigned pos = atomicAdd(&g_cand_cnt[row], 1u);
                    if (pos < CAP)
                        g_cand[(size_t)row * CAP + pos] =
                            ((unsigned long long)fkey(s) << 32) | (unsigned)col;
                }
            }
}

// ---------------- phase 2: exact fp32 refine + fused gather, one warp per row ----
__global__ __launch_bounds__(256) void refine_kernel(const float* __restrict__ X,
                                                     const float* __restrict__ E,
                                                     float* __restrict__ out) {
    const int row = blockIdx.x * 8 + (threadIdx.x >> 5);
    const int lane = threadIdx.x & 31;

    unsigned cnt = g_cand_cnt[row];
    if (cnt > CAP) cnt = CAP;
    const unsigned long long* clist = g_cand + (size_t)row * CAP;
    const float tthr = inv_fkey(g_rowmin_key[row]) + TIGHT;

    unsigned scount = 0, survivor = 0;
    for (unsigned cix = 0; cix < cnt; cix++) {
        const unsigned long long p = clist[cix];
        if (inv_fkey((unsigned)(p >> 32)) <= tthr) { scount++; survivor = (unsigned)p; }
    }

    unsigned widx;
    if (scount == 1) {
        widx = survivor;          // provably the argmin; skip X and all dots
    } else {
        const float4* xr = (const float4*)(X + (size_t)row * DIM);
        float4 xv[8];
#pragma unroll
        for (int i = 0; i < 8; i++) xv[i] = xr[lane + i * 32];

        unsigned long long best = 0xFFFFFFFFFFFFFFFFull;
        for (unsigned cix = 0; cix < cnt; cix++) {
            const unsigned long long p = clist[cix];
            if (inv_fkey((unsigned)(p >> 32)) > tthr) continue;
            const unsigned idx = (unsigned)p;
            const float4* er = (const float4*)(E + (size_t)idx * DIM);
            float dot = 0.f;
#pragma unroll
            for (int i = 0; i < 8; i++) {
                float4 ev = er[lane + i * 32];
                dot = fmaf(xv[i].x, ev.x, dot);
                dot = fmaf(xv[i].y, ev.y, dot);
                dot = fmaf(xv[i].z, ev.z, dot);
                dot = fmaf(xv[i].w, ev.w, dot);
            }
#pragma unroll
            for (int off = 16; off > 0; off >>= 1)
                dot += __shfl_xor_sync(0xffffffffu, dot, off);
            const float s = fmaf(-2.f, dot, g_enorm2[idx]);
            const unsigned long long key = ((unsigned long long)fkey(s) << 32) | idx;
            if (key < best) best = key;
        }
        widx = (unsigned)best;
    }

    const float4* src = (const float4*)(E + (size_t)widx * DIM);
    float4* dst = (float4*)(out + (size_t)row * DIM);
#pragma unroll
    for (int i = 0; i < 8; i++) dst[lane + i * 32] = src[lane + i * 32];
}

// ---------------- launch ----------------
extern "C" void kernel_launch(void* const* d_in, const int* in_sizes, int n_in,
                              void* d_out, int out_size) {
    const float* X = (const float*)d_in[0];
    const float* E = (const float*)d_in[1];
    if (in_sizes[0] == N_CODES * DIM && in_sizes[1] == N_ROWS * DIM) {
        X = (const float*)d_in[1];
        E = (const float*)d_in[0];
    }

    cudaFuncSetAttribute(vq_hmma_kernel, cudaFuncAttributeMaxDynamicSharedMemorySize, SMEM_NEED);

    __nv_bfloat16 *xb_ptr, *eb_ptr;
    cudaGetSymbolAddress((void**)&xb_ptr, g_Xb);
    cudaGetSymbolAddress((void**)&eb_ptr, g_Eb);
    conv_all<<<XCONV_BLOCKS + N_CODES / 8, 256>>>(X, E, xb_ptr, eb_ptr);

    dim3 grid(N_CODES / 128, N_ROWS / 128);   // k-tile fastest: codebook hot in L2
    vq_hmma_kernel<<<grid, 256, SMEM_NEED>>>();

    refine_kernel<<<N_ROWS / 8, 256>>>(X, E, (float*)d_out);
}

// round 16
// speedup vs baseline: 1.0121x; 1.0121x over previous
#include <cuda_runtime.h>
#include <cuda_bf16.h>
#include <cstdint>

#define N_ROWS 16384
#define N_CODES 4096
#define DIM 1024

#define CAP 512                 // candidate list capacity per row
#define MARGIN 14.0f            // >= 2E = 12.6 (worst-case bf16 pair error) + slop
#define TIGHT  12.8f            // >= 2E; singleton within TIGHT -> provably argmin

#define KC 64                   // dims per chunk (64 bf16 = 128B rows, SW128)
#define N_DC (DIM / KC)         // 16 chunks
#define STAGES 3

// ---------------- device scratch (static; no allocation allowed) ----------------
__device__ __nv_bfloat16 g_Xb[N_ROWS * DIM];    // 32 MB
__device__ __nv_bfloat16 g_Eb[N_CODES * DIM];   // 8 MB
__device__ float g_enorm2[N_CODES];
__device__ unsigned int g_rowmin_key[N_ROWS];
__device__ unsigned int g_cand_cnt[N_ROWS];
__device__ unsigned long long g_cand[(size_t)N_ROWS * CAP];  // 64 MB

// ---------------- helpers ----------------
__device__ __forceinline__ unsigned int fkey(float f) {
    unsigned int u = __float_as_uint(f);
    return (u & 0x80000000u) ? ~u : (u | 0x80000000u);
}
__device__ __forceinline__ float inv_fkey(unsigned int k) {
    unsigned int u = (k & 0x80000000u) ? (k ^ 0x80000000u) : ~k;
    return __uint_as_float(u);
}
__device__ __forceinline__ uint32_t smem_u32(const void* p) {
    uint32_t a;
    asm("{ .reg .u64 t; cvta.to.shared.u64 t, %1; cvt.u32.u64 %0, t; }" : "=r"(a) : "l"(p));
    return a;
}
#define SWZ(x) ((x) ^ (((x) >> 3) & 0x70))

__device__ __forceinline__ void cp_async16(uint32_t dst, const void* src) {
    asm volatile("cp.async.cg.shared.global [%0], [%1], 16;"
                 :: "r"(dst), "l"((unsigned long long)__cvta_generic_to_global(src)) : "memory");
}
#define CP_COMMIT()  asm volatile("cp.async.commit_group;" ::: "memory")
#define CP_WAIT(n)   asm volatile("cp.async.wait_group %0;" :: "n"(n) : "memory")

__device__ __forceinline__ void ldmatrix_x4(uint32_t& r0, uint32_t& r1, uint32_t& r2,
                                            uint32_t& r3, uint32_t addr) {
    asm volatile("ldmatrix.sync.aligned.m8n8.x4.shared.b16 {%0,%1,%2,%3}, [%4];"
                 : "=r"(r0), "=r"(r1), "=r"(r2), "=r"(r3) : "r"(addr));
}
__device__ __forceinline__ void mma_16816(float* c, const uint32_t* a, uint32_t b0, uint32_t b1) {
    asm volatile("mma.sync.aligned.m16n8k16.row.col.f32.bf16.bf16.f32 "
                 "{%0,%1,%2,%3}, {%4,%5,%6,%7}, {%8,%9}, {%0,%1,%2,%3};"
                 : "+f"(c[0]), "+f"(c[1]), "+f"(c[2]), "+f"(c[3])
                 : "r"(a[0]), "r"(a[1]), "r"(a[2]), "r"(a[3]), "r"(b0), "r"(b1));
}

// ---------------- phase 0: fused X-convert + state init + E-convert + norms ----
#define XCONV_BLOCKS 2048
__global__ __launch_bounds__(256) void conv_all(const float* __restrict__ X,
                                                const float* __restrict__ E,
                                                __nv_bfloat16* __restrict__ Xb,
                                                __nv_bfloat16* __restrict__ Eb) {
    if (blockIdx.x < XCONV_BLOCKS) {
        int i = blockIdx.x * 256 + threadIdx.x;
        if (i < N_ROWS) { g_rowmin_key[i] = 0xFFFFFFFFu; g_cand_cnt[i] = 0u; }
        const int n4 = N_ROWS * DIM / 4;
        for (; i < n4; i += XCONV_BLOCKS * 256) {
            float4 v = ((const float4*)X)[i];
            ((__nv_bfloat162*)Xb)[i * 2]     = __floats2bfloat162_rn(v.x, v.y);
            ((__nv_bfloat162*)Xb)[i * 2 + 1] = __floats2bfloat162_rn(v.z, v.w);
        }
    } else {
        const int k = (blockIdx.x - XCONV_BLOCKS) * 8 + (threadIdx.x >> 5);
        const int lane = threadIdx.x & 31;
        const float4* row = (const float4*)(E + (size_t)k * DIM);
        __nv_bfloat162* drow = (__nv_bfloat162*)(Eb + (size_t)k * DIM);
        float s = 0.f;
#pragma unroll
        for (int i = 0; i < 8; i++) {
            float4 v = row[lane + i * 32];
            s = fmaf(v.x, v.x, s); s = fmaf(v.y, v.y, s);
            s = fmaf(v.z, v.z, s); s = fmaf(v.w, v.w, s);
            drow[(lane + i * 32) * 2]     = __floats2bfloat162_rn(v.x, v.y);
            drow[(lane + i * 32) * 2 + 1] = __floats2bfloat162_rn(v.z, v.w);
        }
#pragma unroll
        for (int off = 16; off > 0; off >>= 1) s += __shfl_xor_sync(0xffffffffu, s, off);
        if (lane == 0) g_enorm2[k] = s;
    }
}

// ---------------- phase 1: HMMA bf16 GEMM + candidate epilogue ----------------
#define BUF_STRIDE 32768u
#define SMEM_NEED  98304

__device__ __forceinline__ void load_chunk(uint32_t base, int buf, int m0, int k0, int dc, int tid) {
    const uint32_t aB = base + buf * BUF_STRIDE;
    const uint32_t bB = aB + 16384u;
    const __nv_bfloat16* Xsrc = g_Xb + (size_t)m0 * DIM + dc * KC;
    const __nv_bfloat16* Esrc = g_Eb + (size_t)k0 * DIM + dc * KC;
#pragma unroll
    for (int p = 0; p < 4; p++) {
        int s = tid + p * 256;
        int r = s >> 3, c = s & 7;
        cp_async16(aB + SWZ((uint32_t)(r * 128 + c * 16)), Xsrc + (size_t)r * DIM + c * 8);
    }
#pragma unroll
    for (int p = 0; p < 4; p++) {
        int s = tid + p * 256;
        int r = s >> 3, c = s & 7;
        cp_async16(bB + SWZ((uint32_t)(r * 128 + c * 16)), Esrc + (size_t)r * DIM + c * 8);
    }
}

__global__ __launch_bounds__(256, 2) void vq_hmma_kernel() {
    extern __shared__ char smraw[];
    const uint32_t base = smem_u32(smraw);

    const int tid = threadIdx.x;
    const int wid = tid >> 5;
    const int lane = tid & 31;
    const int wm = wid & 3;          // warp M index (4)
    const int wn = wid >> 2;         // warp N index (2)
    const int m0 = blockIdx.y * 128;
    const int k0 = blockIdx.x * 128;

    float c[2][8][4];
#pragma unroll
    for (int i = 0; i < 2; i++)
#pragma unroll
        for (int j = 0; j < 8; j++)
#pragma unroll
            for (int e = 0; e < 4; e++) c[i][j][e] = 0.f;

    const int a_row = wm * 32 + (lane & 15);
    const int a_colb = (lane >> 4) * 16;
    const int bg = lane >> 3;
    const int b_row_base = wn * 64 + ((bg >> 1) * 8) + (lane & 7);
    const int b_colb = (bg & 1) * 16;

    load_chunk(base, 0, m0, k0, 0, tid);
    CP_COMMIT();
    load_chunk(base, 1, m0, k0, 1, tid);
    CP_COMMIT();

    for (int dc = 0; dc < N_DC; dc++) {
        if (dc + 1 < N_DC) CP_WAIT(1); else CP_WAIT(0);
        __syncthreads();

        const uint32_t aB = base + (dc % STAGES) * BUF_STRIDE;
        const uint32_t bB = aB + 16384u;

        // kk = 0 and kk = 1 first: two sub-blocks of tensor work before the
        // cp.async issue burst contends for issue slots
#pragma unroll
        for (int kk = 0; kk < 2; kk++) {
            uint32_t a[2][4];
#pragma unroll
            for (int i = 0; i < 2; i++)
                ldmatrix_x4(a[i][0], a[i][1], a[i][2], a[i][3],
                            aB + SWZ((uint32_t)((a_row + i * 16) * 128 + kk * 32 + a_colb)));
            uint32_t b[4][4];
#pragma unroll
            for (int j2 = 0; j2 < 4; j2++)
                ldmatrix_x4(b[j2][0], b[j2][1], b[j2][2], b[j2][3],
                            bB + SWZ((uint32_t)((b_row_base + j2 * 16) * 128 + kk * 32 + b_colb)));
#pragma unroll
            for (int i = 0; i < 2; i++)
#pragma unroll
                for (int j2 = 0; j2 < 4; j2++) {
                    mma_16816(c[i][j2 * 2],     a[i], b[j2][0], b[j2][1]);
                    mma_16816(c[i][j2 * 2 + 1], a[i], b[j2][2], b[j2][3]);
                }
        }

        // monolithic prefetch of chunk dc+2 (still ~1.5 chunks ahead of use)
        if (dc + 2 < N_DC) {
            load_chunk(base, (dc + 2) % STAGES, m0, k0, dc + 2, tid);
            CP_COMMIT();
        }

#pragma unroll
        for (int kk = 2; kk < 4; kk++) {
            uint32_t a[2][4];
#pragma unroll
            for (int i = 0; i < 2; i++)
                ldmatrix_x4(a[i][0], a[i][1], a[i][2], a[i][3],
                            aB + SWZ((uint32_t)((a_row + i * 16) * 128 + kk * 32 + a_colb)));
            uint32_t b[4][4];
#pragma unroll
            for (int j2 = 0; j2 < 4; j2++)
                ldmatrix_x4(b[j2][0], b[j2][1], b[j2][2], b[j2][3],
                            bB + SWZ((uint32_t)((b_row_base + j2 * 16) * 128 + kk * 32 + b_colb)));
#pragma unroll
            for (int i = 0; i < 2; i++)
#pragma unroll
                for (int j2 = 0; j2 < 4; j2++) {
                    mma_16816(c[i][j2 * 2],     a[i], b[j2][0], b[j2][1]);
                    mma_16816(c[i][j2 * 2 + 1], a[i], b[j2][2], b[j2][3]);
                }
        }
    }

    // ---- epilogue ----
    const int qrow = lane >> 2;
    const int qcol = (lane & 3) * 2;

    float rmin[4] = {__int_as_float(0x7f800000), __int_as_float(0x7f800000),
                     __int_as_float(0x7f800000), __int_as_float(0x7f800000)};
#pragma unroll
    for (int i = 0; i < 2; i++)
#pragma unroll
        for (int j = 0; j < 8; j++) {
            const int colb = k0 + wn * 64 + j * 8 + qcol;
            const float en0 = __ldg(&g_enorm2[colb]);
            const float en1 = __ldg(&g_enorm2[colb + 1]);
#pragma unroll
            for (int e = 0; e < 4; e++) {
                const float s = fmaf(-2.f, c[i][j][e], (e & 1) ? en1 : en0);
                c[i][j][e] = s;
                const int r = i * 2 + (e >> 1);
                rmin[r] = fminf(rmin[r], s);
            }
        }
#pragma unroll
    for (int r = 0; r < 4; r++) {
#pragma unroll
        for (int off = 1; off < 4; off <<= 1)
            rmin[r] = fminf(rmin[r], __shfl_xor_sync(0xffffffffu, rmin[r], off));
    }
    int rows[4];
#pragma unroll
    for (int r = 0; r < 4; r++)
        rows[r] = m0 + wm * 32 + (r >> 1) * 16 + qrow + (r & 1) * 8;

    if ((lane & 3) == 0) {
#pragma unroll
        for (int r = 0; r < 4; r++) {
            const unsigned key = fkey(rmin[r]);
            if (key < g_rowmin_key[rows[r]])          // cheap L2 read filters ~97% of atomics
                atomicMin(&g_rowmin_key[rows[r]], key);
        }
    }

    float thr[4];
#pragma unroll
    for (int r = 0; r < 4; r++) {
        const float g = inv_fkey(g_rowmin_key[rows[r]]);
        thr[r] = fminf(rmin[r], g) + MARGIN;
    }
#pragma unroll
    for (int i = 0; i < 2; i++)
#pragma unroll
        for (int j = 0; j < 8; j++)
#pragma unroll
            for (int e = 0; e < 4; e++) {
                const int r = i * 2 + (e >> 1);
                const float s = c[i][j][e];
                if (s <= thr[r]) {
                    const int row = rows[r];
                    const int col = k0 + wn * 64 + j * 8 + qcol + (e & 1);
                    unsigned pos = atomicAdd(&g_cand_cnt[row], 1u);
                    if (pos < CAP)
                        g_cand[(size_t)row * CAP + pos] =
                            ((unsigned long long)fkey(s) << 32) | (unsigned)col;
                }
            }
}

// ---------------- phase 2: exact fp32 refine + fused gather, one warp per row ----
__global__ __launch_bounds__(256) void refine_kernel(const float* __restrict__ X,
                                                     const float* __restrict__ E,
                                                     float* __restrict__ out) {
    const int row = blockIdx.x * 8 + (threadIdx.x >> 5);
    const int lane = threadIdx.x & 31;

    unsigned cnt = g_cand_cnt[row];
    if (cnt > CAP) cnt = CAP;
    const unsigned long long* clist = g_cand + (size_t)row * CAP;
    const float tthr = inv_fkey(g_rowmin_key[row]) + TIGHT;

    unsigned scount = 0, survivor = 0;
    for (unsigned cix = 0; cix < cnt; cix++) {
        const unsigned long long p = clist[cix];
        if (inv_fkey((unsigned)(p >> 32)) <= tthr) { scount++; survivor = (unsigned)p; }
    }

    unsigned widx;
    if (scount == 1) {
        widx = survivor;          // provably the argmin; skip X and all dots
    } else {
        const float4* xr = (const float4*)(X + (size_t)row * DIM);
        float4 xv[8];
#pragma unroll
        for (int i = 0; i < 8; i++) xv[i] = xr[lane + i * 32];

        unsigned long long best = 0xFFFFFFFFFFFFFFFFull;
        for (unsigned cix = 0; cix < cnt; cix++) {
            const unsigned long long p = clist[cix];
            if (inv_fkey((unsigned)(p >> 32)) > tthr) continue;
            const unsigned idx = (unsigned)p;
            const float4* er = (const float4*)(E + (size_t)idx * DIM);
            float dot = 0.f;
#pragma unroll
            for (int i = 0; i < 8; i++) {
                float4 ev = er[lane + i * 32];
                dot = fmaf(xv[i].x, ev.x, dot);
                dot = fmaf(xv[i].y, ev.y, dot);
                dot = fmaf(xv[i].z, ev.z, dot);
                dot = fmaf(xv[i].w, ev.w, dot);
            }
#pragma unroll
            for (int off = 16; off > 0; off >>= 1)
                dot += __shfl_xor_sync(0xffffffffu, dot, off);
            const float s = fmaf(-2.f, dot, g_enorm2[idx]);
            const unsigned long long key = ((unsigned long long)fkey(s) << 32) | idx;
            if (key < best) best = key;
        }
        widx = (unsigned)best;
    }

    const float4* src = (const float4*)(E + (size_t)widx * DIM);
    float4* dst = (float4*)(out + (size_t)row * DIM);
#pragma unroll
    for (int i = 0; i < 8; i++) dst[lane + i * 32] = src[lane + i * 32];
}

// ---------------- launch ----------------
extern "C" void kernel_launch(void* const* d_in, const int* in_sizes, int n_in,
                              void* d_out, int out_size) {
    const float* X = (const float*)d_in[0];
    const float* E = (const float*)d_in[1];
    if (in_sizes[0] == N_CODES * DIM && in_sizes[1] == N_ROWS * DIM) {
        X = (const float*)d_in[1];
        E = (const float*)d_in[0];
    }

    cudaFuncSetAttribute(vq_hmma_kernel, cudaFuncAttributeMaxDynamicSharedMemorySize, SMEM_NEED);

    __nv_bfloat16 *xb_ptr, *eb_ptr;
    cudaGetSymbolAddress((void**)&xb_ptr, g_Xb);
    cudaGetSymbolAddress((void**)&eb_ptr, g_Eb);
    conv_all<<<XCONV_BLOCKS + N_CODES / 8, 256>>>(X, E, xb_ptr, eb_ptr);

    dim3 grid(N_CODES / 128, N_ROWS / 128);   // k-tile fastest: codebook hot in L2
    vq_hmma_kernel<<<grid, 256, SMEM_NEED>>>();

    refine_kernel<<<N_ROWS / 8, 256>>>(X, E, (float*)d_out);
}

// round 17
// speedup vs baseline: 1.0204x; 1.0082x over previous
#include <cuda_runtime.h>
#include <cuda_bf16.h>
#include <cstdint>

#define N_ROWS 16384
#define N_CODES 4096
#define DIM 1024

#define CAP 512                 // candidate list capacity per row
#define MARGIN 14.0f            // >= 2E = 12.6 (worst-case bf16 pair error) + slop
#define TIGHT  12.8f            // >= 2E; singleton within TIGHT -> provably argmin

#define KC 64                   // dims per chunk (64 bf16 = 128B rows, SW128)
#define N_DC (DIM / KC)         // 16 chunks
#define STAGES 3

// ---------------- device scratch (static; no allocation allowed) ----------------
__device__ __nv_bfloat16 g_Xb[N_ROWS * DIM];    // 32 MB
__device__ __nv_bfloat16 g_Eb[N_CODES * DIM];   // 8 MB
__device__ float g_enorm2[N_CODES];
__device__ unsigned int g_rowmin_key[N_ROWS];
__device__ unsigned int g_cand_cnt[N_ROWS];
__device__ unsigned long long g_cand[(size_t)N_ROWS * CAP];  // 64 MB

// ---------------- helpers ----------------
__device__ __forceinline__ unsigned int fkey(float f) {
    unsigned int u = __float_as_uint(f);
    return (u & 0x80000000u) ? ~u : (u | 0x80000000u);
}
__device__ __forceinline__ float inv_fkey(unsigned int k) {
    unsigned int u = (k & 0x80000000u) ? (k ^ 0x80000000u) : ~k;
    return __uint_as_float(u);
}
__device__ __forceinline__ uint32_t smem_u32(const void* p) {
    uint32_t a;
    asm("{ .reg .u64 t; cvta.to.shared.u64 t, %1; cvt.u32.u64 %0, t; }" : "=r"(a) : "l"(p));
    return a;
}
#define SWZ(x) ((x) ^ (((x) >> 3) & 0x70))

__device__ __forceinline__ void cp_async16(uint32_t dst, const void* src) {
    asm volatile("cp.async.cg.shared.global [%0], [%1], 16;"
                 :: "r"(dst), "l"((unsigned long long)__cvta_generic_to_global(src)) : "memory");
}
#define CP_COMMIT()  asm volatile("cp.async.commit_group;" ::: "memory")
#define CP_WAIT(n)   asm volatile("cp.async.wait_group %0;" :: "n"(n) : "memory")

__device__ __forceinline__ void ldmatrix_x4(uint32_t& r0, uint32_t& r1, uint32_t& r2,
                                            uint32_t& r3, uint32_t addr) {
    asm volatile("ldmatrix.sync.aligned.m8n8.x4.shared.b16 {%0,%1,%2,%3}, [%4];"
                 : "=r"(r0), "=r"(r1), "=r"(r2), "=r"(r3) : "r"(addr));
}
__device__ __forceinline__ void mma_16816(float* c, const uint32_t* a, uint32_t b0, uint32_t b1) {
    asm volatile("mma.sync.aligned.m16n8k16.row.col.f32.bf16.bf16.f32 "
                 "{%0,%1,%2,%3}, {%4,%5,%6,%7}, {%8,%9}, {%0,%1,%2,%3};"
                 : "+f"(c[0]), "+f"(c[1]), "+f"(c[2]), "+f"(c[3])
                 : "r"(a[0]), "r"(a[1]), "r"(a[2]), "r"(a[3]), "r"(b0), "r"(b1));
}

// ---------------- phase 0: fused X-convert + state init + E-convert + norms ----
#define XCONV_BLOCKS 2048
__global__ __launch_bounds__(256) void conv_all(const float* __restrict__ X,
                                                const float* __restrict__ E,
                                                __nv_bfloat16* __restrict__ Xb,
                                                __nv_bfloat16* __restrict__ Eb) {
    if (blockIdx.x < XCONV_BLOCKS) {
        int i = blockIdx.x * 256 + threadIdx.x;
        if (i < N_ROWS) { g_rowmin_key[i] = 0xFFFFFFFFu; g_cand_cnt[i] = 0u; }
        const int n4 = N_ROWS * DIM / 4;
        for (; i < n4; i += XCONV_BLOCKS * 256) {
            float4 v = ((const float4*)X)[i];
            ((__nv_bfloat162*)Xb)[i * 2]     = __floats2bfloat162_rn(v.x, v.y);
            ((__nv_bfloat162*)Xb)[i * 2 + 1] = __floats2bfloat162_rn(v.z, v.w);
        }
    } else {
        const int k = (blockIdx.x - XCONV_BLOCKS) * 8 + (threadIdx.x >> 5);
        const int lane = threadIdx.x & 31;
        const float4* row = (const float4*)(E + (size_t)k * DIM);
        __nv_bfloat162* drow = (__nv_bfloat162*)(Eb + (size_t)k * DIM);
        float s = 0.f;
#pragma unroll
        for (int i = 0; i < 8; i++) {
            float4 v = row[lane + i * 32];
            s = fmaf(v.x, v.x, s); s = fmaf(v.y, v.y, s);
            s = fmaf(v.z, v.z, s); s = fmaf(v.w, v.w, s);
            drow[(lane + i * 32) * 2]     = __floats2bfloat162_rn(v.x, v.y);
            drow[(lane + i * 32) * 2 + 1] = __floats2bfloat162_rn(v.z, v.w);
        }
#pragma unroll
        for (int off = 16; off > 0; off >>= 1) s += __shfl_xor_sync(0xffffffffu, s, off);
        if (lane == 0) g_enorm2[k] = s;
    }
}

// ---------------- phase 1: HMMA bf16 GEMM + candidate epilogue ----------------
#define BUF_STRIDE 32768u
#define SMEM_NEED  98304

__device__ __forceinline__ void load_chunk(uint32_t base, int buf, int m0, int k0, int dc, int tid) {
    const uint32_t aB = base + buf * BUF_STRIDE;
    const uint32_t bB = aB + 16384u;
    const __nv_bfloat16* Xsrc = g_Xb + (size_t)m0 * DIM + dc * KC;
    const __nv_bfloat16* Esrc = g_Eb + (size_t)k0 * DIM + dc * KC;
#pragma unroll
    for (int p = 0; p < 4; p++) {
        int s = tid + p * 256;
        int r = s >> 3, c = s & 7;
        cp_async16(aB + SWZ((uint32_t)(r * 128 + c * 16)), Xsrc + (size_t)r * DIM + c * 8);
    }
#pragma unroll
    for (int p = 0; p < 4; p++) {
        int s = tid + p * 256;
        int r = s >> 3, c = s & 7;
        cp_async16(bB + SWZ((uint32_t)(r * 128 + c * 16)), Esrc + (size_t)r * DIM + c * 8);
    }
}

__global__ __launch_bounds__(256, 2) void vq_hmma_kernel() {
    extern __shared__ char smraw[];
    const uint32_t base = smem_u32(smraw);

    const int tid = threadIdx.x;
    const int wid = tid >> 5;
    const int lane = tid & 31;
    const int wm = wid & 3;          // warp M index (4)
    const int wn = wid >> 2;         // warp N index (2)
    const int m0 = blockIdx.y * 128;
    const int k0 = blockIdx.x * 128;

    float c[2][8][4];
#pragma unroll
    for (int i = 0; i < 2; i++)
#pragma unroll
        for (int j = 0; j < 8; j++)
#pragma unroll
            for (int e = 0; e < 4; e++) c[i][j][e] = 0.f;

    const int a_row = wm * 32 + (lane & 15);
    const int a_colb = (lane >> 4) * 16;
    const int bg = lane >> 3;
    const int b_row_base = wn * 64 + ((bg >> 1) * 8) + (lane & 7);
    const int b_colb = (bg & 1) * 16;

    load_chunk(base, 0, m0, k0, 0, tid);
    CP_COMMIT();
    load_chunk(base, 1, m0, k0, 1, tid);
    CP_COMMIT();

    for (int dc = 0; dc < N_DC; dc++) {
        if (dc + 1 < N_DC) CP_WAIT(1); else CP_WAIT(0);
        __syncthreads();

        const uint32_t aB = base + (dc % STAGES) * BUF_STRIDE;
        const uint32_t bB = aB + 16384u;

        // kk = 0 first: get the tensor pipe going before the cp.async issue burst
        {
            uint32_t a[2][4];
#pragma unroll
            for (int i = 0; i < 2; i++)
                ldmatrix_x4(a[i][0], a[i][1], a[i][2], a[i][3],
                            aB + SWZ((uint32_t)((a_row + i * 16) * 128 + a_colb)));
            uint32_t b[4][4];
#pragma unroll
            for (int j2 = 0; j2 < 4; j2++)
                ldmatrix_x4(b[j2][0], b[j2][1], b[j2][2], b[j2][3],
                            bB + SWZ((uint32_t)((b_row_base + j2 * 16) * 128 + b_colb)));
#pragma unroll
            for (int i = 0; i < 2; i++)
#pragma unroll
                for (int j2 = 0; j2 < 4; j2++) {
                    mma_16816(c[i][j2 * 2],     a[i], b[j2][0], b[j2][1]);
                    mma_16816(c[i][j2 * 2 + 1], a[i], b[j2][2], b[j2][3]);
                }
        }

        // prefetch chunk dc+2 (still ~1.75 chunks ahead of its consumption)
        if (dc + 2 < N_DC) {
            load_chunk(base, (dc + 2) % STAGES, m0, k0, dc + 2, tid);
            CP_COMMIT();
        }

#pragma unroll
        for (int kk = 1; kk < 4; kk++) {
            uint32_t a[2][4];
#pragma unroll
            for (int i = 0; i < 2; i++)
                ldmatrix_x4(a[i][0], a[i][1], a[i][2], a[i][3],
                            aB + SWZ((uint32_t)((a_row + i * 16) * 128 + kk * 32 + a_colb)));
            uint32_t b[4][4];
#pragma unroll
            for (int j2 = 0; j2 < 4; j2++)
                ldmatrix_x4(b[j2][0], b[j2][1], b[j2][2], b[j2][3],
                            bB + SWZ((uint32_t)((b_row_base + j2 * 16) * 128 + kk * 32 + b_colb)));
#pragma unroll
            for (int i = 0; i < 2; i++)
#pragma unroll
                for (int j2 = 0; j2 < 4; j2++) {
                    mma_16816(c[i][j2 * 2],     a[i], b[j2][0], b[j2][1]);
                    mma_16816(c[i][j2 * 2 + 1], a[i], b[j2][2], b[j2][3]);
                }
        }
    }

    // ---- epilogue ----
    const int qrow = lane >> 2;
    const int qcol = (lane & 3) * 2;

    float rmin[4] = {__int_as_float(0x7f800000), __int_as_float(0x7f800000),
                     __int_as_float(0x7f800000), __int_as_float(0x7f800000)};
#pragma unroll
    for (int i = 0; i < 2; i++)
#pragma unroll
        for (int j = 0; j < 8; j++) {
            const int colb = k0 + wn * 64 + j * 8 + qcol;
            const float en0 = __ldg(&g_enorm2[colb]);
            const float en1 = __ldg(&g_enorm2[colb + 1]);
#pragma unroll
            for (int e = 0; e < 4; e++) {
                const float s = fmaf(-2.f, c[i][j][e], (e & 1) ? en1 : en0);
                c[i][j][e] = s;
                const int r = i * 2 + (e >> 1);
                rmin[r] = fminf(rmin[r], s);
            }
        }
#pragma unroll
    for (int r = 0; r < 4; r++) {
#pragma unroll
        for (int off = 1; off < 4; off <<= 1)
            rmin[r] = fminf(rmin[r], __shfl_xor_sync(0xffffffffu, rmin[r], off));
    }
    int rows[4];
#pragma unroll
    for (int r = 0; r < 4; r++)
        rows[r] = m0 + wm * 32 + (r >> 1) * 16 + qrow + (r & 1) * 8;

    if ((lane & 3) == 0) {
#pragma unroll
        for (int r = 0; r < 4; r++) {
            const unsigned key = fkey(rmin[r]);
            if (key < g_rowmin_key[rows[r]])          // cheap L2 read filters ~97% of atomics
                atomicMin(&g_rowmin_key[rows[r]], key);
        }
    }

    float thr[4];
#pragma unroll
    for (int r = 0; r < 4; r++) {
        const float g = inv_fkey(g_rowmin_key[rows[r]]);
        thr[r] = fminf(rmin[r], g) + MARGIN;
    }
#pragma unroll
    for (int i = 0; i < 2; i++)
#pragma unroll
        for (int j = 0; j < 8; j++)
#pragma unroll
            for (int e = 0; e < 4; e++) {
                const int r = i * 2 + (e >> 1);
                const float s = c[i][j][e];
                if (s <= thr[r]) {
                    const int row = rows[r];
                    const int col = k0 + wn * 64 + j * 8 + qcol + (e & 1);
                    unsigned pos = atomicAdd(&g_cand_cnt[row], 1u);
                    if (pos < CAP)
                        g_cand[(size_t)row * CAP + pos] =
                            ((unsigned long long)fkey(s) << 32) | (unsigned)col;
                }
            }
}

// ---------------- phase 2: exact fp32 refine + fused gather, one warp per row ----
__global__ __launch_bounds__(256) void refine_kernel(const float* __restrict__ X,
                                                     const float* __restrict__ E,
                                                     float* __restrict__ out) {
    const int row = blockIdx.x * 8 + (threadIdx.x >> 5);
    const int lane = threadIdx.x & 31;

    unsigned cnt = g_cand_cnt[row];
    if (cnt > CAP) cnt = CAP;
    const unsigned long long* clist = g_cand + (size_t)row * CAP;
    const float tthr = inv_fkey(g_rowmin_key[row]) + TIGHT;

    unsigned scount = 0, survivor = 0;
    for (unsigned cix = 0; cix < cnt; cix++) {
        const unsigned long long p = clist[cix];
        if (inv_fkey((unsigned)(p >> 32)) <= tthr) { scount++; survivor = (unsigned)p; }
    }

    unsigned widx;
    if (scount == 1) {
        widx = survivor;          // provably the argmin; skip X and all dots
    } else {
        const float4* xr = (const float4*)(X + (size_t)row * DIM);
        float4 xv[8];
#pragma unroll
        for (int i = 0; i < 8; i++) xv[i] = xr[lane + i * 32];

        unsigned long long best = 0xFFFFFFFFFFFFFFFFull;
        for (unsigned cix = 0; cix < cnt; cix++) {
            const unsigned long long p = clist[cix];
            if (inv_fkey((unsigned)(p >> 32)) > tthr) continue;
            const unsigned idx = (unsigned)p;
            const float4* er = (const float4*)(E + (size_t)idx * DIM);
            float dot = 0.f;
#pragma unroll
            for (int i = 0; i < 8; i++) {
                float4 ev = er[lane + i * 32];
                dot = fmaf(xv[i].x, ev.x, dot);
                dot = fmaf(xv[i].y, ev.y, dot);
                dot = fmaf(xv[i].z, ev.z, dot);
                dot = fmaf(xv[i].w, ev.w, dot);
            }
#pragma unroll
            for (int off = 16; off > 0; off >>= 1)
                dot += __shfl_xor_sync(0xffffffffu, dot, off);
            const float s = fmaf(-2.f, dot, g_enorm2[idx]);
            const unsigned long long key = ((unsigned long long)fkey(s) << 32) | idx;
            if (key < best) best = key;
        }
        widx = (unsigned)best;
    }

    const float4* src = (const float4*)(E + (size_t)widx * DIM);
    float4* dst = (float4*)(out + (size_t)row * DIM);
#pragma unroll
    for (int i = 0; i < 8; i++) dst[lane + i * 32] = src[lane + i * 32];
}

// ---------------- launch ----------------
extern "C" void kernel_launch(void* const* d_in, const int* in_sizes, int n_in,
                              void* d_out, int out_size) {
    const float* X = (const float*)d_in[0];
    const float* E = (const float*)d_in[1];
    if (in_sizes[0] == N_CODES * DIM && in_sizes[1] == N_ROWS * DIM) {
        X = (const float*)d_in[1];
        E = (const float*)d_in[0];
    }

    cudaFuncSetAttribute(vq_hmma_kernel, cudaFuncAttributeMaxDynamicSharedMemorySize, SMEM_NEED);

    __nv_bfloat16 *xb_ptr, *eb_ptr;
    cudaGetSymbolAddress((void**)&xb_ptr, g_Xb);
    cudaGetSymbolAddress((void**)&eb_ptr, g_Eb);
    conv_all<<<XCONV_BLOCKS + N_CODES / 8, 256>>>(X, E, xb_ptr, eb_ptr);

    dim3 grid(N_CODES / 128, N_ROWS / 128);   // k-tile fastest: codebook hot in L2
    vq_hmma_kernel<<<grid, 256, SMEM_NEED>>>();

    refine_kernel<<<N_ROWS / 8, 256>>>(X, E, (float*)d_out);
}